// round 12
// baseline (speedup 1.0000x reference)
#include <cuda_runtime.h>

// QConv1D quantum sim, R12: closed-form transfer-matrix DP (see R9),
// warp-self-contained (no smem, no barriers).
//  R12 delta vs R9: TWO sims per thread (positions t and t+4072) -> 64 CTAs
//  instead of 128 (tests per-CTA launch/drain component). The two DP chains
//  interleave as pure ILP; critical path unchanged.
constexpr int O_CH  = 8;
constexpr int NQ    = 8;
constexpr int L_IN  = 512;
constexpr int L_OUT = 509;
constexpr int B_SZ  = 16;
constexpr int N_POS = B_SZ * L_OUT;          // 8144
constexpr int HALF  = N_POS / 2;             // 4072
constexpr int TPB   = 512;
constexpr int POS_PER_BLK = TPB / O_CH;      // 64 pairs per block

__global__ __launch_bounds__(TPB)
void qconv_kernel(const float* __restrict__ x,
                  const float* __restrict__ w,
                  float* __restrict__ out)
{
    const int tid  = threadIdx.x;
    const int lane = tid & 31;
    const int u    = lane & 7;               // o-channel AND x-trig qubit
    const int g    = lane >> 3;              // 0..3: weight-trig q slot

    // --- two sim positions per thread: n1 = t, n2 = t + 4072
    const int t_raw = blockIdx.x * POS_PER_BLK + (tid >> 3);
    const bool valid = (t_raw < HALF);
    const int n1  = valid ? t_raw : HALF - 1;
    const int n2  = n1 + HALF;
    const int bb1 = n1 / L_OUT, pos1 = n1 - bb1 * L_OUT;
    const int bb2 = n2 / L_OUT, pos2 = n2 - bb2 * L_OUT;
    // lane u's x values for qubit q=u at both positions (loads issued first)
    const float xv1 = x[(bb1 * 2 + (u >> 2)) * L_IN + pos1 + (u & 3)];
    const float xv2 = x[(bb2 * 2 + (u >> 2)) * L_IN + pos2 + (u & 3)];

    // --- weight loads for (o=u, q=g) and (o=u, q=g+4); w layout (O, NQ, 2)
    const float2 wa = reinterpret_cast<const float2*>(w)[u * NQ + g];
    const float2 wb = reinterpret_cast<const float2*>(w)[u * NQ + g + 4];

    float c0a, s0a, c1a, s1a, c0b, s0b, c1b, s1b;
    float cx1, sx1, cx2, sx2;
    __sincosf(xv1, &sx1, &cx1);
    __sincosf(xv2, &sx2, &cx2);
    __sincosf(wa.x, &s0a, &c0a);
    __sincosf(wa.y, &s1a, &c1a);
    __sincosf(wb.x, &s0b, &c0b);
    __sincosf(wb.y, &s1b, &c1b);

    // --- output indexing for both sims (overlaps trig latency)
    //     flat sim s = u*8144 + n, reinterpreted as [b'][p'][o']
    const int oo1 = n1 & 7, nh1 = n1 >> 3;
    const int hi1 = (nh1 >= L_OUT) ? 1 : 0;
    float* const optr1 = out + ((2 * u + hi1) * O_CH + oo1) * L_OUT + (nh1 - hi1 * L_OUT);
    const int oo2 = n2 & 7, nh2 = n2 >> 3;
    const int hi2 = (nh2 >= L_OUT) ? 1 : 0;
    float* const optr2 = out + ((2 * u + hi2) * O_CH + oo2) * L_OUT + (nh2 - hi2 * L_OUT);

    const int gbase = lane & 24;             // 8-lane group base within warp

    // --- two interleaved 3-state transfer-matrix DPs over the 8-qubit chain
    float a00 = 1.f, a01 = 1.f, a10 = 0.f;   // sim 1
    float b00 = 1.f, b01 = 1.f, b10 = 0.f;   // sim 2
#pragma unroll
    for (int q = 0; q < NQ; q++) {
        const int wsrc = u + ((q & 3) << 3);
        const float c0 = __shfl_sync(0xffffffffu, (q < 4) ? c0a : c0b, wsrc);
        const float s0 = __shfl_sync(0xffffffffu, (q < 4) ? s0a : s0b, wsrc);
        const float c1 = __shfl_sync(0xffffffffu, (q < 4) ? c1a : c1b, wsrc);
        const float s1 = __shfl_sync(0xffffffffu, (q < 4) ? s1a : s1b, wsrc);
        const float cq1 = __shfl_sync(0xffffffffu, cx1, gbase + q);
        const float sq1 = __shfl_sync(0xffffffffu, sx1, gbase + q);
        const float cq2 = __shfl_sync(0xffffffffu, cx2, gbase + q);
        const float sq2 = __shfl_sync(0xffffffffu, sx2, gbase + q);

        const float C1 = cq1 * c0 - sq1 * s0;        // cos(x1+p0)
        const float S1 = sq1 * c0 + cq1 * s0;        // sin(x1+p0)
        const float C2 = cq2 * c0 - sq2 * s0;
        const float S2 = sq2 * c0 + cq2 * s0;

        const float u1 = -s1 * S1;
        const float u2 = -s1 * S2;
        const float m00 = c1 * fmaf(a00, C1, a10);
        const float m01 = c1 * fmaf(a10, C1, a00);
        const float m10 = u1 * a01;
        const float p00 = c1 * fmaf(b00, C2, b10);
        const float p01 = c1 * fmaf(b10, C2, b00);
        const float p10 = u2 * b01;
        a00 = m00; a01 = m01; a10 = m10;
        b00 = p00; b01 = p01; b10 = p10;
    }

    if (valid) {
        *optr1 = a00 + a10;                  // boundary b_8 = 0
        *optr2 = b00 + b10;
    }
}

extern "C" void kernel_launch(void* const* d_in, const int* in_sizes, int n_in,
                              void* d_out, int out_size)
{
    const float* x = (const float*)d_in[0];
    const float* w = (const float*)d_in[1];
    float* out = (float*)d_out;
    const int blocks = (HALF + POS_PER_BLK - 1) / POS_PER_BLK;   // 64
    qconv_kernel<<<blocks, TPB>>>(x, w, out);
}